// round 12
// baseline (speedup 1.0000x reference)
#include <cuda_runtime.h>
#include <cuda_fp16.h>
#include <math.h>
#include <stdint.h>

// ---------------------------------------------------------------------------
// Affinity GAT (2-layer GATv2). CSR-by-dst with 4-record-padded segments
// (branch-free 4-edge groups, masked pads, 128-bit edge-record loads) +
// direct-exp softmax edge kernels (1 warp/node, fp16 xl gathers) + tf32 MMA
// GEMMs; CSR build overlapped with layer-1 GEMMs. N=50000, E=800000.
// ---------------------------------------------------------------------------

#define N_MAX 51200
#define E_MAX 810000
#define EX_MAX (E_MAX + 4 * N_MAX)     // padded segments: sum(cnt+4) worst case
#define NCHUNK_MAX 64

__device__ int   g_cnt[N_MAX];
__device__ float g_attrsum[N_MAX];
__device__ int   g_fill[N_MAX];
__device__ int   g_rowptr[N_MAX + 1];
__device__ int   g_chunksum[NCHUNK_MAX];
__device__ int   g_chunkoff[NCHUNK_MAX];
__device__ __align__(16) int2 g_epack[EX_MAX];
__device__ __align__(256) __half g_xlh [(size_t)N_MAX * 128];  // layer-1 fp16 src features
__device__ __align__(256) float  g_xr  [(size_t)N_MAX * 128];  // layer-1 fp32 dst features
__device__ __align__(256) float  g_h   [(size_t)N_MAX * 128];  // layer-1 output
__device__ __align__(256) __half g_xlh2[(size_t)N_MAX * 64];   // layer-2 fp16 src features
__device__ __align__(256) float  g_xr2 [(size_t)N_MAX * 64];   // layer-2 fp32 dst features

// ---------------------------------------------------------------------------
__global__ void k_zero(int n) {
    int i = blockIdx.x * blockDim.x + threadIdx.x;
    if (i < n) { g_cnt[i] = 0; g_attrsum[i] = 0.f; g_fill[i] = 0; }
}

__global__ void k_count(const int* __restrict__ dst, const float* __restrict__ ea, int E) {
    int e = blockIdx.x * blockDim.x + threadIdx.x;
    if (e < E) {
        int d = dst[e];
        atomicAdd(&g_cnt[d], 1);
        atomicAdd(&g_attrsum[d], ea[e]);
    }
}

// Padded segment length for node i: round (cnt+1) up to a multiple of 4.
__device__ __forceinline__ int pad_len(int cnt) { return (cnt + 4) & ~3; }

// ---- 3-phase parallel scan of pad_len(cnt[i]) -> rowptr ----
__global__ void k_scan1(int n) {
    __shared__ int ws[32];
    int warp = threadIdx.x >> 5, lane = threadIdx.x & 31;
    int i = blockIdx.x * 1024 + threadIdx.x;
    int v = (i < n) ? pad_len(g_cnt[i]) : 0;
    #pragma unroll
    for (int o = 16; o; o >>= 1) v += __shfl_xor_sync(0xffffffffu, v, o);
    if (lane == 0) ws[warp] = v;
    __syncthreads();
    if (warp == 0) {
        int t = ws[lane];
        #pragma unroll
        for (int o = 16; o; o >>= 1) t += __shfl_xor_sync(0xffffffffu, t, o);
        if (lane == 0) g_chunksum[blockIdx.x] = t;
    }
}

__global__ void k_scan2(int nch) {
    int lane = threadIdx.x;
    int a = (lane < nch) ? g_chunksum[lane] : 0;
    int b = (lane + 32 < nch) ? g_chunksum[lane + 32] : 0;
    int ai = a, bi = b;
    #pragma unroll
    for (int o = 1; o < 32; o <<= 1) {
        int t = __shfl_up_sync(0xffffffffu, ai, o);
        if (lane >= o) ai += t;
        int u = __shfl_up_sync(0xffffffffu, bi, o);
        if (lane >= o) bi += u;
    }
    int totA = __shfl_sync(0xffffffffu, ai, 31);
    if (lane < nch)      g_chunkoff[lane]      = ai - a;
    if (lane + 32 < nch) g_chunkoff[lane + 32] = totA + bi - b;
}

__global__ void k_scan3(int n, int nch) {
    __shared__ int wsum[32];
    int warp = threadIdx.x >> 5, lane = threadIdx.x & 31;
    int i = blockIdx.x * 1024 + threadIdx.x;
    int carry = g_chunkoff[blockIdx.x];
    int v = (i < n) ? pad_len(g_cnt[i]) : 0;
    int s = v;
    #pragma unroll
    for (int o = 1; o < 32; o <<= 1) {
        int t = __shfl_up_sync(0xffffffffu, s, o);
        if (lane >= o) s += t;
    }
    if (lane == 31) wsum[warp] = s;
    __syncthreads();
    if (warp == 0) {
        int ws = wsum[lane];
        #pragma unroll
        for (int o = 1; o < 32; o <<= 1) {
            int t = __shfl_up_sync(0xffffffffu, ws, o);
            if (lane >= o) ws += t;
        }
        wsum[lane] = ws;
    }
    __syncthreads();
    int warp_prefix = (warp > 0) ? wsum[warp - 1] : 0;
    if (i < n) g_rowptr[i] = carry + warp_prefix + s - v;
    if (blockIdx.x == nch - 1 && threadIdx.x == 0) g_rowptr[n] = carry + wsum[31];
}

// Scatter real edges + self loop; self-loop thread also writes the <=3 pad
// records (src=-1, a=0 -> masked to weight 0 in the edge kernel).
__global__ void k_scatter(const int* __restrict__ src, const int* __restrict__ dst,
                          const float* __restrict__ ea, int E, int n) {
    int t = blockIdx.x * blockDim.x + threadIdx.x;
    if (t < E) {
        int d = dst[t];
        int pos = g_rowptr[d] + atomicAdd(&g_fill[d], 1);
        g_epack[pos] = make_int2(src[t], __float_as_int(ea[t]));
    } else if (t < E + n) {
        int i = t - E;
        int c = g_cnt[i];
        float la = g_attrsum[i] / (float)(c > 1 ? c : 1);
        int pos = g_rowptr[i] + atomicAdd(&g_fill[i], 1);
        g_epack[pos] = make_int2(i, __float_as_int(la));
        // pad records: slots [rowptr[i]+c+1, rowptr[i+1])
        int pbeg = g_rowptr[i] + c + 1;
        int pend = g_rowptr[i + 1];
        for (int p = pbeg; p < pend; p++)
            g_epack[p] = make_int2(-1, 0);
    }
}

// ---------------------------------------------------------------------------
// tf32 helpers
// ---------------------------------------------------------------------------
__device__ __forceinline__ uint32_t f2tf32(float x) {
    uint32_t u;
    asm("cvt.rna.tf32.f32 %0, %1;" : "=r"(u) : "f"(x));
    return u;
}

__device__ __forceinline__ void mma_tf32(float& c0, float& c1, float& c2, float& c3,
                                         uint32_t a0, uint32_t a1, uint32_t a2, uint32_t a3,
                                         uint32_t b0, uint32_t b1) {
    asm volatile(
        "mma.sync.aligned.m16n8k8.row.col.f32.tf32.tf32.f32 "
        "{%0,%1,%2,%3}, {%4,%5,%6,%7}, {%8,%9}, {%0,%1,%2,%3};"
        : "+f"(c0), "+f"(c1), "+f"(c2), "+f"(c3)
        : "r"(a0), "r"(a1), "r"(a2), "r"(a3), "r"(b0), "r"(b1));
}

// Output store helpers (fp32 or fp16 feature matrices)
__device__ __forceinline__ void store_pair(float* out, size_t idx, float a, float b) {
    *(float2*)(out + idx) = make_float2(a, b);
}
__device__ __forceinline__ void store_pair(__half* out, size_t idx, float a, float b) {
    *(__half2*)(out + idx) = __floats2half2_rn(a, b);
}

// ---------------------------------------------------------------------------
// Single-output GEMM: out[N,NC] = A[N,128] @ W[128,NC] (tf32 mma).
// ---------------------------------------------------------------------------
template<int NC, typename OutT>
__global__ __launch_bounds__(256) void k_gemm_mma(const float* __restrict__ A,
                                                  const float* __restrict__ W,
                                                  OutT* __restrict__ out, int n) {
    constexpr int K   = 128;
    constexpr int SAS = 132;
    constexpr int SWS = (NC == 128) ? 136 : 72;
    constexpr int NT  = NC / 8;

    extern __shared__ float sh[];
    float* As = sh;
    float* Ws = sh + 128 * SAS;

    const int tid  = threadIdx.x;
    const int warp = tid >> 5;
    const int lane = tid & 31;
    const int g    = lane >> 2;
    const int t    = lane & 3;

    for (int i4 = tid; i4 < K * NC / 4; i4 += 256) {
        int idx = i4 * 4;
        int k = idx / NC, c = idx % NC;
        float4 w = *(const float4*)(W + idx);
        uint32_t* p = (uint32_t*)(Ws + k * SWS + c);
        p[0] = f2tf32(w.x); p[1] = f2tf32(w.y); p[2] = f2tf32(w.z); p[3] = f2tf32(w.w);
    }

    const int rb = blockIdx.x * 128;
    for (int i4 = tid; i4 < 128 * 32; i4 += 256) {
        int r = i4 >> 5, c = (i4 & 31) * 4;
        float4 a = make_float4(0.f, 0.f, 0.f, 0.f);
        if (rb + r < n) a = *(const float4*)(A + (size_t)(rb + r) * K + c);
        uint32_t* p = (uint32_t*)(As + r * SAS + c);
        p[0] = f2tf32(a.x); p[1] = f2tf32(a.y); p[2] = f2tf32(a.z); p[3] = f2tf32(a.w);
    }
    __syncthreads();

    float acc[NT][4];
    #pragma unroll
    for (int nt = 0; nt < NT; nt++)
        #pragma unroll
        for (int c = 0; c < 4; c++) acc[nt][c] = 0.f;

    const int r0 = warp * 16;
    const uint32_t* Au = (const uint32_t*)As;
    const uint32_t* Wu = (const uint32_t*)Ws;

    #pragma unroll 4
    for (int kk = 0; kk < K / 8; kk++) {
        int kb = kk * 8;
        uint32_t a0 = Au[(r0 + g)     * SAS + kb + t];
        uint32_t a1 = Au[(r0 + g + 8) * SAS + kb + t];
        uint32_t a2 = Au[(r0 + g)     * SAS + kb + t + 4];
        uint32_t a3 = Au[(r0 + g + 8) * SAS + kb + t + 4];
        #pragma unroll
        for (int nt = 0; nt < NT; nt++) {
            uint32_t b0 = Wu[(kb + t)     * SWS + nt * 8 + g];
            uint32_t b1 = Wu[(kb + t + 4) * SWS + nt * 8 + g];
            mma_tf32(acc[nt][0], acc[nt][1], acc[nt][2], acc[nt][3],
                     a0, a1, a2, a3, b0, b1);
        }
    }

    int row0 = rb + r0 + g;
    int row1 = row0 + 8;
    #pragma unroll
    for (int nt = 0; nt < NT; nt++) {
        int col = nt * 8 + 2 * t;
        if (row0 < n) store_pair(out, (size_t)row0 * NC + col, acc[nt][0], acc[nt][1]);
        if (row1 < n) store_pair(out, (size_t)row1 * NC + col, acc[nt][2], acc[nt][3]);
    }
}

// ---------------------------------------------------------------------------
// Dual-output GEMM (layer 2, NC=64): out1 (fp16) = A@W1, out2 (fp32) = A@W2.
// ---------------------------------------------------------------------------
__global__ __launch_bounds__(256) void k_gemm_mma_dual64(const float* __restrict__ A,
                                                         const float* __restrict__ W1,
                                                         const float* __restrict__ W2,
                                                         __half* __restrict__ out1,
                                                         float* __restrict__ out2, int n) {
    constexpr int K   = 128;
    constexpr int NC  = 64;
    constexpr int SAS = 132;
    constexpr int SWS = 72;
    constexpr int NT  = NC / 8;

    extern __shared__ float sh[];
    float* As  = sh;
    float* W1s = sh + 128 * SAS;
    float* W2s = W1s + K * SWS;

    const int tid  = threadIdx.x;
    const int warp = tid >> 5;
    const int lane = tid & 31;
    const int g    = lane >> 2;
    const int t    = lane & 3;

    for (int i4 = tid; i4 < K * NC / 4; i4 += 256) {
        int idx = i4 * 4;
        int k = idx / NC, c = idx % NC;
        float4 w1 = *(const float4*)(W1 + idx);
        float4 w2 = *(const float4*)(W2 + idx);
        uint32_t* p1 = (uint32_t*)(W1s + k * SWS + c);
        uint32_t* p2 = (uint32_t*)(W2s + k * SWS + c);
        p1[0] = f2tf32(w1.x); p1[1] = f2tf32(w1.y); p1[2] = f2tf32(w1.z); p1[3] = f2tf32(w1.w);
        p2[0] = f2tf32(w2.x); p2[1] = f2tf32(w2.y); p2[2] = f2tf32(w2.z); p2[3] = f2tf32(w2.w);
    }

    const int rb = blockIdx.x * 128;
    for (int i4 = tid; i4 < 128 * 32; i4 += 256) {
        int r = i4 >> 5, c = (i4 & 31) * 4;
        float4 a = make_float4(0.f, 0.f, 0.f, 0.f);
        if (rb + r < n) a = *(const float4*)(A + (size_t)(rb + r) * K + c);
        uint32_t* p = (uint32_t*)(As + r * SAS + c);
        p[0] = f2tf32(a.x); p[1] = f2tf32(a.y); p[2] = f2tf32(a.z); p[3] = f2tf32(a.w);
    }
    __syncthreads();

    float acc1[NT][4], acc2[NT][4];
    #pragma unroll
    for (int nt = 0; nt < NT; nt++)
        #pragma unroll
        for (int c = 0; c < 4; c++) { acc1[nt][c] = 0.f; acc2[nt][c] = 0.f; }

    const int r0 = warp * 16;
    const uint32_t* Au  = (const uint32_t*)As;
    const uint32_t* W1u = (const uint32_t*)W1s;
    const uint32_t* W2u = (const uint32_t*)W2s;

    #pragma unroll 4
    for (int kk = 0; kk < K / 8; kk++) {
        int kb = kk * 8;
        uint32_t a0 = Au[(r0 + g)     * SAS + kb + t];
        uint32_t a1 = Au[(r0 + g + 8) * SAS + kb + t];
        uint32_t a2 = Au[(r0 + g)     * SAS + kb + t + 4];
        uint32_t a3 = Au[(r0 + g + 8) * SAS + kb + t + 4];
        #pragma unroll
        for (int nt = 0; nt < NT; nt++) {
            uint32_t b0 = W1u[(kb + t)     * SWS + nt * 8 + g];
            uint32_t b1 = W1u[(kb + t + 4) * SWS + nt * 8 + g];
            mma_tf32(acc1[nt][0], acc1[nt][1], acc1[nt][2], acc1[nt][3],
                     a0, a1, a2, a3, b0, b1);
            uint32_t c0 = W2u[(kb + t)     * SWS + nt * 8 + g];
            uint32_t c1 = W2u[(kb + t + 4) * SWS + nt * 8 + g];
            mma_tf32(acc2[nt][0], acc2[nt][1], acc2[nt][2], acc2[nt][3],
                     a0, a1, a2, a3, c0, c1);
        }
    }

    int row0 = rb + r0 + g;
    int row1 = row0 + 8;
    #pragma unroll
    for (int nt = 0; nt < NT; nt++) {
        int col = nt * 8 + 2 * t;
        if (row0 < n) {
            store_pair(out1, (size_t)row0 * NC + col, acc1[nt][0], acc1[nt][1]);
            store_pair(out2, (size_t)row0 * NC + col, acc2[nt][0], acc2[nt][1]);
        }
        if (row1 < n) {
            store_pair(out1, (size_t)row1 * NC + col, acc1[nt][2], acc1[nt][3]);
            store_pair(out2, (size_t)row1 * NC + col, acc2[nt][2], acc2[nt][3]);
        }
    }
}

// ---------------------------------------------------------------------------
// Fused edge phase: one warp per dst node, direct-exp softmax. Segments are
// padded to multiples of 4 records -> branch-free full 4-edge groups,
// 128-bit edge-record loads, pad mask via src<0. fp16 xl gathers.
// ---------------------------------------------------------------------------
template<int C>
__global__ void k_edge(const __half* __restrict__ xl, const float* __restrict__ xr,
                       const float* __restrict__ We, const float* __restrict__ att,
                       const float* __restrict__ bias, float* __restrict__ out, int n) {
    constexpr int PC = C / 32;          // 4 or 2 floats per lane
    int w = (blockIdx.x * blockDim.x + threadIdx.x) >> 5;
    int lane = threadIdx.x & 31;
    if (w >= n) return;
    const int i = w;
    const int start = g_rowptr[i], end = g_rowptr[i + 1];   // end-start % 4 == 0

    float xrv[PC], Wev[PC], attv[PC], bv[PC];
    #pragma unroll
    for (int c = 0; c < PC; c++) {
        int col = lane * PC + c;
        xrv[c]  = xr[(size_t)i * C + col];
        Wev[c]  = We[col];
        attv[c] = att[col];
        bv[c]   = bias[col];
    }

    float ssum = 0.f;
    float acc[PC];
    #pragma unroll
    for (int c = 0; c < PC; c++) acc[c] = 0.f;

    for (int e = start; e < end; e += 4) {
        // 32B of edge records via two 16B loads (e is 4-aligned)
        uint4 q0 = *(const uint4*)(g_epack + e);
        uint4 q1 = *(const uint4*)(g_epack + e + 2);
        int   srcj[4] = { (int)q0.x, (int)q0.z, (int)q1.x, (int)q1.z };
        float aj[4]   = { __uint_as_float(q0.y), __uint_as_float(q0.w),
                          __uint_as_float(q1.y), __uint_as_float(q1.w) };

        float xv[4][PC];
        #pragma unroll
        for (int j = 0; j < 4; j++) {
            int s = srcj[j] >= 0 ? srcj[j] : 0;            // safe addr for pads
            const __half* xp = xl + (size_t)s * C + lane * PC;
            if (PC == 4) {
                uint2 u = *(const uint2*)xp;
                float2 f0 = __half22float2(*reinterpret_cast<__half2*>(&u.x));
                float2 f1 = __half22float2(*reinterpret_cast<__half2*>(&u.y));
                xv[j][0] = f0.x; xv[j][1] = f0.y; xv[j][2] = f1.x; xv[j][3] = f1.y;
            } else {
                uint32_t u = *(const uint32_t*)xp;
                float2 f0 = __half22float2(*reinterpret_cast<__half2*>(&u));
                xv[j][0] = f0.x; xv[j][1] = f0.y;
            }
        }

        float p[4];
        #pragma unroll
        for (int j = 0; j < 4; j++) {
            float s = 0.f;
            #pragma unroll
            for (int c = 0; c < PC; c++) {
                float u = xv[j][c] + xrv[c] + aj[j] * Wev[c];
                u = u > 0.f ? u : 0.2f * u;                // leaky_relu(0.2)
                s += attv[c] * u;
            }
            p[j] = s;
        }
        #pragma unroll
        for (int o = 16; o; o >>= 1) {
            #pragma unroll
            for (int j = 0; j < 4; j++)
                p[j] += __shfl_xor_sync(0xffffffffu, p[j], o);
        }

        float wg[4];
        #pragma unroll
        for (int j = 0; j < 4; j++)
            wg[j] = srcj[j] >= 0 ? __expf(p[j]) : 0.f;     // pads contribute 0
        ssum += (wg[0] + wg[1]) + (wg[2] + wg[3]);
        #pragma unroll
        for (int c = 0; c < PC; c++) {
            float t0 = wg[0] * xv[0][c] + wg[1] * xv[1][c];
            float t1 = wg[2] * xv[2][c] + wg[3] * xv[3][c];
            acc[c] += t0 + t1;
        }
    }

    float inv = 1.f / (ssum + 1e-16f);
    float ov[PC];
    #pragma unroll
    for (int c = 0; c < PC; c++) {
        float o = acc[c] * inv + bv[c];
        ov[c] = o > 0.f ? o : (__expf(o) - 1.f);           // ELU
    }
    if (PC == 4)
        *(float4*)(out + (size_t)i * C + lane * 4) = make_float4(ov[0], ov[1], ov[2], ov[3]);
    else
        *(float2*)(out + (size_t)i * C + lane * 2) = make_float2(ov[0], ov[1]);
}

// ---------------------------------------------------------------------------
extern "C" void kernel_launch(void* const* d_in, const int* in_sizes, int n_in,
                              void* d_out, int out_size) {
    const float* x    = (const float*)d_in[0];
    const int*   eidx = (const int*)  d_in[1];
    const float* ea   = (const float*)d_in[2];
    const float* Wl1  = (const float*)d_in[3];
    const float* Wr1  = (const float*)d_in[4];
    const float* We1  = (const float*)d_in[5];
    const float* att1 = (const float*)d_in[6];
    const float* b1   = (const float*)d_in[7];
    const float* Wl2  = (const float*)d_in[8];
    const float* Wr2  = (const float*)d_in[9];
    const float* We2  = (const float*)d_in[10];
    const float* att2 = (const float*)d_in[11];
    const float* b2   = (const float*)d_in[12];

    const int N = in_sizes[0] / 128;
    const int E = in_sizes[2];
    if (N > N_MAX || E > E_MAX) return;
    const int NCH = (N + 1023) / 1024;
    if (NCH > NCHUNK_MAX) return;

    const int* src = eidx;
    const int* dst = eidx + E;

    __half *p_xlh, *p_xlh2;
    float *p_xr, *p_h, *p_xr2;
    cudaGetSymbolAddress((void**)&p_xlh,  g_xlh);
    cudaGetSymbolAddress((void**)&p_xr,   g_xr);
    cudaGetSymbolAddress((void**)&p_h,    g_h);
    cudaGetSymbolAddress((void**)&p_xlh2, g_xlh2);
    cudaGetSymbolAddress((void**)&p_xr2,  g_xr2);

    const size_t smA  = (size_t)128 * 132 * sizeof(float);
    const size_t sm1  = smA + (size_t)128 * 136 * sizeof(float);
    const size_t sm2d = smA + (size_t)2 * 128 * 72 * sizeof(float);
    cudaFuncSetAttribute((const void*)k_gemm_mma<128, __half>,
                         cudaFuncAttributeMaxDynamicSharedMemorySize, (int)sm1);
    cudaFuncSetAttribute((const void*)k_gemm_mma<128, float>,
                         cudaFuncAttributeMaxDynamicSharedMemorySize, (int)sm1);
    cudaFuncSetAttribute((const void*)k_gemm_mma_dual64,
                         cudaFuncAttributeMaxDynamicSharedMemorySize, (int)sm2d);

    int gemm_grid = (N + 127) / 128;
    int edge_grid = (N + 7) / 8;       // 8 warps/block, 1 warp/node

    // ---- Fork: layer-1 GEMMs (stream s1) || CSR build (default stream) ----
    cudaStream_t s1;
    cudaEvent_t evFork, evJoin;
    cudaStreamCreateWithFlags(&s1, cudaStreamNonBlocking);
    cudaEventCreateWithFlags(&evFork, cudaEventDisableTiming);
    cudaEventCreateWithFlags(&evJoin, cudaEventDisableTiming);

    cudaEventRecord(evFork, 0);
    cudaStreamWaitEvent(s1, evFork, 0);

    k_gemm_mma<128, __half><<<gemm_grid, 256, sm1, s1>>>(x, Wl1, p_xlh, N);
    k_gemm_mma<128, float ><<<gemm_grid, 256, sm1, s1>>>(x, Wr1, p_xr,  N);
    cudaEventRecord(evJoin, s1);

    k_zero   <<<(N + 255) / 256, 256>>>(N);
    k_count  <<<(E + 255) / 256, 256>>>(dst, ea, E);
    k_scan1  <<<NCH, 1024>>>(N);
    k_scan2  <<<1, 32>>>(NCH);
    k_scan3  <<<NCH, 1024>>>(N, NCH);
    k_scatter<<<(E + N + 255) / 256, 256>>>(src, dst, ea, E, N);

    cudaStreamWaitEvent(0, evJoin, 0);   // xl1/xr1 ready before edge phase

    // ---- Linear tail (proven fastest schedule) ----
    k_edge<128><<<edge_grid, 256>>>(p_xlh, p_xr, We1, att1, b1, p_h, N);
    k_gemm_mma_dual64<<<gemm_grid, 256, sm2d>>>(p_h, Wl2, Wr2, p_xlh2, p_xr2, N);
    k_edge<64><<<edge_grid, 256>>>(p_xlh2, p_xr2, We2, att2, b2, (float*)d_out, N);

    cudaEventDestroy(evFork);
    cudaEventDestroy(evJoin);
    cudaStreamDestroy(s1);
}

// round 13
// speedup vs baseline: 1.1122x; 1.1122x over previous
#include <cuda_runtime.h>
#include <cuda_fp16.h>
#include <math.h>
#include <stdint.h>

// ---------------------------------------------------------------------------
// Affinity GAT (2-layer GATv2). CSR-by-dst + fused edge kernel (direct-exp
// softmax, 1 warp/node, 4-edge unroll, fp16 xl gathers, 128-thread blocks)
// + tf32 MMA GEMMs; CSR build overlapped with layer-1 GEMMs.
// N=50000, E=800000.  (R8 configuration + smaller edge blocks.)
// ---------------------------------------------------------------------------

#define N_MAX 51200
#define E_MAX 810000
#define EX_MAX (E_MAX + N_MAX)
#define NCHUNK_MAX 64

__device__ int   g_cnt[N_MAX];
__device__ float g_attrsum[N_MAX];
__device__ int   g_fill[N_MAX];
__device__ int   g_rowptr[N_MAX + 1];
__device__ int   g_chunksum[NCHUNK_MAX];
__device__ int   g_chunkoff[NCHUNK_MAX];
__device__ __align__(8) int2 g_epack[EX_MAX];
__device__ __align__(256) __half g_xlh[(size_t)N_MAX * 128];   // fp16 source-side features
__device__ __align__(256) float  g_xr [(size_t)N_MAX * 128];   // fp32 target-side features
__device__ __align__(256) float  g_h  [(size_t)N_MAX * 128];   // fp32 layer-1 output

// ---------------------------------------------------------------------------
__global__ void k_zero(int n) {
    int i = blockIdx.x * blockDim.x + threadIdx.x;
    if (i < n) { g_cnt[i] = 0; g_attrsum[i] = 0.f; g_fill[i] = 0; }
}

__global__ void k_count(const int* __restrict__ dst, const float* __restrict__ ea, int E) {
    int e = blockIdx.x * blockDim.x + threadIdx.x;
    if (e < E) {
        int d = dst[e];
        atomicAdd(&g_cnt[d], 1);
        atomicAdd(&g_attrsum[d], ea[e]);
    }
}

// ---- 3-phase parallel scan of (cnt[i]+1) -> rowptr ----
__global__ void k_scan1(int n) {
    __shared__ int ws[32];
    int warp = threadIdx.x >> 5, lane = threadIdx.x & 31;
    int i = blockIdx.x * 1024 + threadIdx.x;
    int v = (i < n) ? (g_cnt[i] + 1) : 0;
    #pragma unroll
    for (int o = 16; o; o >>= 1) v += __shfl_xor_sync(0xffffffffu, v, o);
    if (lane == 0) ws[warp] = v;
    __syncthreads();
    if (warp == 0) {
        int t = ws[lane];
        #pragma unroll
        for (int o = 16; o; o >>= 1) t += __shfl_xor_sync(0xffffffffu, t, o);
        if (lane == 0) g_chunksum[blockIdx.x] = t;
    }
}

__global__ void k_scan2(int nch) {
    int lane = threadIdx.x;
    int a = (lane < nch) ? g_chunksum[lane] : 0;
    int b = (lane + 32 < nch) ? g_chunksum[lane + 32] : 0;
    int ai = a, bi = b;
    #pragma unroll
    for (int o = 1; o < 32; o <<= 1) {
        int t = __shfl_up_sync(0xffffffffu, ai, o);
        if (lane >= o) ai += t;
        int u = __shfl_up_sync(0xffffffffu, bi, o);
        if (lane >= o) bi += u;
    }
    int totA = __shfl_sync(0xffffffffu, ai, 31);
    if (lane < nch)      g_chunkoff[lane]      = ai - a;
    if (lane + 32 < nch) g_chunkoff[lane + 32] = totA + bi - b;
}

__global__ void k_scan3(int n, int nch) {
    __shared__ int wsum[32];
    int warp = threadIdx.x >> 5, lane = threadIdx.x & 31;
    int i = blockIdx.x * 1024 + threadIdx.x;
    int carry = g_chunkoff[blockIdx.x];
    int v = (i < n) ? (g_cnt[i] + 1) : 0;
    int s = v;
    #pragma unroll
    for (int o = 1; o < 32; o <<= 1) {
        int t = __shfl_up_sync(0xffffffffu, s, o);
        if (lane >= o) s += t;
    }
    if (lane == 31) wsum[warp] = s;
    __syncthreads();
    if (warp == 0) {
        int ws = wsum[lane];
        #pragma unroll
        for (int o = 1; o < 32; o <<= 1) {
            int t = __shfl_up_sync(0xffffffffu, ws, o);
            if (lane >= o) ws += t;
        }
        wsum[lane] = ws;
    }
    __syncthreads();
    int warp_prefix = (warp > 0) ? wsum[warp - 1] : 0;
    if (i < n) g_rowptr[i] = carry + warp_prefix + s - v;
    if (blockIdx.x == nch - 1 && threadIdx.x == 0) g_rowptr[n] = carry + wsum[31];
}

__global__ void k_scatter(const int* __restrict__ src, const int* __restrict__ dst,
                          const float* __restrict__ ea, int E, int n) {
    int t = blockIdx.x * blockDim.x + threadIdx.x;
    if (t < E) {
        int d = dst[t];
        int pos = g_rowptr[d] + atomicAdd(&g_fill[d], 1);
        g_epack[pos] = make_int2(src[t], __float_as_int(ea[t]));
    } else if (t < E + n) {
        int i = t - E;
        int c = g_cnt[i];
        float la = g_attrsum[i] / (float)(c > 1 ? c : 1);
        int pos = g_rowptr[i] + atomicAdd(&g_fill[i], 1);
        g_epack[pos] = make_int2(i, __float_as_int(la));
    }
}

// ---------------------------------------------------------------------------
// tf32 helpers
// ---------------------------------------------------------------------------
__device__ __forceinline__ uint32_t f2tf32(float x) {
    uint32_t u;
    asm("cvt.rna.tf32.f32 %0, %1;" : "=r"(u) : "f"(x));
    return u;
}

__device__ __forceinline__ void mma_tf32(float& c0, float& c1, float& c2, float& c3,
                                         uint32_t a0, uint32_t a1, uint32_t a2, uint32_t a3,
                                         uint32_t b0, uint32_t b1) {
    asm volatile(
        "mma.sync.aligned.m16n8k8.row.col.f32.tf32.tf32.f32 "
        "{%0,%1,%2,%3}, {%4,%5,%6,%7}, {%8,%9}, {%0,%1,%2,%3};"
        : "+f"(c0), "+f"(c1), "+f"(c2), "+f"(c3)
        : "r"(a0), "r"(a1), "r"(a2), "r"(a3), "r"(b0), "r"(b1));
}

// Output store helpers (fp32 or fp16 feature matrices)
__device__ __forceinline__ void store_pair(float* out, size_t idx, float a, float b) {
    *(float2*)(out + idx) = make_float2(a, b);
}
__device__ __forceinline__ void store_pair(__half* out, size_t idx, float a, float b) {
    *(__half2*)(out + idx) = __floats2half2_rn(a, b);
}

// ---------------------------------------------------------------------------
// Single-output GEMM: out[N,NC] = A[N,128] @ W[128,NC] (tf32 mma).
// ---------------------------------------------------------------------------
template<int NC, typename OutT>
__global__ __launch_bounds__(256) void k_gemm_mma(const float* __restrict__ A,
                                                  const float* __restrict__ W,
                                                  OutT* __restrict__ out, int n) {
    constexpr int K   = 128;
    constexpr int SAS = 132;
    constexpr int SWS = (NC == 128) ? 136 : 72;
    constexpr int NT  = NC / 8;

    extern __shared__ float sh[];
    float* As = sh;
    float* Ws = sh + 128 * SAS;

    const int tid  = threadIdx.x;
    const int warp = tid >> 5;
    const int lane = tid & 31;
    const int g    = lane >> 2;
    const int t    = lane & 3;

    for (int i4 = tid; i4 < K * NC / 4; i4 += 256) {
        int idx = i4 * 4;
        int k = idx / NC, c = idx % NC;
        float4 w = *(const float4*)(W + idx);
        uint32_t* p = (uint32_t*)(Ws + k * SWS + c);
        p[0] = f2tf32(w.x); p[1] = f2tf32(w.y); p[2] = f2tf32(w.z); p[3] = f2tf32(w.w);
    }

    const int rb = blockIdx.x * 128;
    for (int i4 = tid; i4 < 128 * 32; i4 += 256) {
        int r = i4 >> 5, c = (i4 & 31) * 4;
        float4 a = make_float4(0.f, 0.f, 0.f, 0.f);
        if (rb + r < n) a = *(const float4*)(A + (size_t)(rb + r) * K + c);
        uint32_t* p = (uint32_t*)(As + r * SAS + c);
        p[0] = f2tf32(a.x); p[1] = f2tf32(a.y); p[2] = f2tf32(a.z); p[3] = f2tf32(a.w);
    }
    __syncthreads();

    float acc[NT][4];
    #pragma unroll
    for (int nt = 0; nt < NT; nt++)
        #pragma unroll
        for (int c = 0; c < 4; c++) acc[nt][c] = 0.f;

    const int r0 = warp * 16;
    const uint32_t* Au = (const uint32_t*)As;
    const uint32_t* Wu = (const uint32_t*)Ws;

    #pragma unroll 4
    for (int kk = 0; kk < K / 8; kk++) {
        int kb = kk * 8;
        uint32_t a0 = Au[(r0 + g)     * SAS + kb + t];
        uint32_t a1 = Au[(r0 + g + 8) * SAS + kb + t];
        uint32_t a2 = Au[(r0 + g)     * SAS + kb + t + 4];
        uint32_t a3 = Au[(r0 + g + 8) * SAS + kb + t + 4];
        #pragma unroll
        for (int nt = 0; nt < NT; nt++) {
            uint32_t b0 = Wu[(kb + t)     * SWS + nt * 8 + g];
            uint32_t b1 = Wu[(kb + t + 4) * SWS + nt * 8 + g];
            mma_tf32(acc[nt][0], acc[nt][1], acc[nt][2], acc[nt][3],
                     a0, a1, a2, a3, b0, b1);
        }
    }

    int row0 = rb + r0 + g;
    int row1 = row0 + 8;
    #pragma unroll
    for (int nt = 0; nt < NT; nt++) {
        int col = nt * 8 + 2 * t;
        if (row0 < n) store_pair(out, (size_t)row0 * NC + col, acc[nt][0], acc[nt][1]);
        if (row1 < n) store_pair(out, (size_t)row1 * NC + col, acc[nt][2], acc[nt][3]);
    }
}

// ---------------------------------------------------------------------------
// Dual-output GEMM (layer 2, NC=64): out1 (fp16) = A@W1, out2 (fp32) = A@W2.
// ---------------------------------------------------------------------------
__global__ __launch_bounds__(256) void k_gemm_mma_dual64(const float* __restrict__ A,
                                                         const float* __restrict__ W1,
                                                         const float* __restrict__ W2,
                                                         __half* __restrict__ out1,
                                                         float* __restrict__ out2, int n) {
    constexpr int K   = 128;
    constexpr int NC  = 64;
    constexpr int SAS = 132;
    constexpr int SWS = 72;
    constexpr int NT  = NC / 8;

    extern __shared__ float sh[];
    float* As  = sh;
    float* W1s = sh + 128 * SAS;
    float* W2s = W1s + K * SWS;

    const int tid  = threadIdx.x;
    const int warp = tid >> 5;
    const int lane = tid & 31;
    const int g    = lane >> 2;
    const int t    = lane & 3;

    for (int i4 = tid; i4 < K * NC / 4; i4 += 256) {
        int idx = i4 * 4;
        int k = idx / NC, c = idx % NC;
        float4 w1 = *(const float4*)(W1 + idx);
        float4 w2 = *(const float4*)(W2 + idx);
        uint32_t* p1 = (uint32_t*)(W1s + k * SWS + c);
        uint32_t* p2 = (uint32_t*)(W2s + k * SWS + c);
        p1[0] = f2tf32(w1.x); p1[1] = f2tf32(w1.y); p1[2] = f2tf32(w1.z); p1[3] = f2tf32(w1.w);
        p2[0] = f2tf32(w2.x); p2[1] = f2tf32(w2.y); p2[2] = f2tf32(w2.z); p2[3] = f2tf32(w2.w);
    }

    const int rb = blockIdx.x * 128;
    for (int i4 = tid; i4 < 128 * 32; i4 += 256) {
        int r = i4 >> 5, c = (i4 & 31) * 4;
        float4 a = make_float4(0.f, 0.f, 0.f, 0.f);
        if (rb + r < n) a = *(const float4*)(A + (size_t)(rb + r) * K + c);
        uint32_t* p = (uint32_t*)(As + r * SAS + c);
        p[0] = f2tf32(a.x); p[1] = f2tf32(a.y); p[2] = f2tf32(a.z); p[3] = f2tf32(a.w);
    }
    __syncthreads();

    float acc1[NT][4], acc2[NT][4];
    #pragma unroll
    for (int nt = 0; nt < NT; nt++)
        #pragma unroll
        for (int c = 0; c < 4; c++) { acc1[nt][c] = 0.f; acc2[nt][c] = 0.f; }

    const int r0 = warp * 16;
    const uint32_t* Au  = (const uint32_t*)As;
    const uint32_t* W1u = (const uint32_t*)W1s;
    const uint32_t* W2u = (const uint32_t*)W2s;

    #pragma unroll 4
    for (int kk = 0; kk < K / 8; kk++) {
        int kb = kk * 8;
        uint32_t a0 = Au[(r0 + g)     * SAS + kb + t];
        uint32_t a1 = Au[(r0 + g + 8) * SAS + kb + t];
        uint32_t a2 = Au[(r0 + g)     * SAS + kb + t + 4];
        uint32_t a3 = Au[(r0 + g + 8) * SAS + kb + t + 4];
        #pragma unroll
        for (int nt = 0; nt < NT; nt++) {
            uint32_t b0 = W1u[(kb + t)     * SWS + nt * 8 + g];
            uint32_t b1 = W1u[(kb + t + 4) * SWS + nt * 8 + g];
            mma_tf32(acc1[nt][0], acc1[nt][1], acc1[nt][2], acc1[nt][3],
                     a0, a1, a2, a3, b0, b1);
            uint32_t c0 = W2u[(kb + t)     * SWS + nt * 8 + g];
            uint32_t c1 = W2u[(kb + t + 4) * SWS + nt * 8 + g];
            mma_tf32(acc2[nt][0], acc2[nt][1], acc2[nt][2], acc2[nt][3],
                     a0, a1, a2, a3, c0, c1);
        }
    }

    int row0 = rb + r0 + g;
    int row1 = row0 + 8;
    #pragma unroll
    for (int nt = 0; nt < NT; nt++) {
        int col = nt * 8 + 2 * t;
        if (row0 < n) {
            store_pair(out1, (size_t)row0 * NC + col, acc1[nt][0], acc1[nt][1]);
            store_pair(out2, (size_t)row0 * NC + col, acc2[nt][0], acc2[nt][1]);
        }
        if (row1 < n) {
            store_pair(out1, (size_t)row1 * NC + col, acc1[nt][2], acc1[nt][3]);
            store_pair(out2, (size_t)row1 * NC + col, acc2[nt][2], acc2[nt][3]);
        }
    }
}

// ---------------------------------------------------------------------------
// Fused edge phase (R8 structure, 128-thread blocks): one warp per dst node,
// direct-exp softmax, 4-edge unroll, fp16 xl gathers.
// ---------------------------------------------------------------------------
template<int C>
__global__ __launch_bounds__(128) void k_edge(const __half* __restrict__ xl,
                                              const float* __restrict__ xr,
                                              const float* __restrict__ We,
                                              const float* __restrict__ att,
                                              const float* __restrict__ bias,
                                              float* __restrict__ out, int n) {
    constexpr int PC = C / 32;          // 4 or 2 floats per lane
    int w = (blockIdx.x * blockDim.x + threadIdx.x) >> 5;
    int lane = threadIdx.x & 31;
    if (w >= n) return;
    const int i = w;
    const int start = g_rowptr[i], end = g_rowptr[i + 1];

    float xrv[PC], Wev[PC], attv[PC], bv[PC];
    #pragma unroll
    for (int c = 0; c < PC; c++) {
        int col = lane * PC + c;
        xrv[c]  = xr[(size_t)i * C + col];
        Wev[c]  = We[col];
        attv[c] = att[col];
        bv[c]   = bias[col];
    }

    float ssum = 0.f;
    float acc[PC];
    #pragma unroll
    for (int c = 0; c < PC; c++) acc[c] = 0.f;

    int e = start;
    for (; e + 4 <= end; e += 4) {
        int2 pk[4];
        #pragma unroll
        for (int j = 0; j < 4; j++) pk[j] = g_epack[e + j];

        float xv[4][PC];
        #pragma unroll
        for (int j = 0; j < 4; j++) {
            const __half* xp = xl + (size_t)pk[j].x * C + lane * PC;
            if (PC == 4) {
                uint2 u = *(const uint2*)xp;
                float2 f0 = __half22float2(*reinterpret_cast<__half2*>(&u.x));
                float2 f1 = __half22float2(*reinterpret_cast<__half2*>(&u.y));
                xv[j][0] = f0.x; xv[j][1] = f0.y; xv[j][2] = f1.x; xv[j][3] = f1.y;
            } else {
                uint32_t u = *(const uint32_t*)xp;
                float2 f0 = __half22float2(*reinterpret_cast<__half2*>(&u));
                xv[j][0] = f0.x; xv[j][1] = f0.y;
            }
        }

        float p[4];
        #pragma unroll
        for (int j = 0; j < 4; j++) {
            float a = __int_as_float(pk[j].y);
            float s = 0.f;
            #pragma unroll
            for (int c = 0; c < PC; c++) {
                float u = xv[j][c] + xrv[c] + a * Wev[c];
                u = u > 0.f ? u : 0.2f * u;               // leaky_relu(0.2)
                s += attv[c] * u;
            }
            p[j] = s;
        }
        #pragma unroll
        for (int o = 16; o; o >>= 1) {
            #pragma unroll
            for (int j = 0; j < 4; j++)
                p[j] += __shfl_xor_sync(0xffffffffu, p[j], o);
        }

        float wg[4];
        #pragma unroll
        for (int j = 0; j < 4; j++) wg[j] = __expf(p[j]);
        ssum += (wg[0] + wg[1]) + (wg[2] + wg[3]);
        #pragma unroll
        for (int c = 0; c < PC; c++) {
            float t0 = wg[0] * xv[0][c] + wg[1] * xv[1][c];
            float t1 = wg[2] * xv[2][c] + wg[3] * xv[3][c];
            acc[c] += t0 + t1;
        }
    }
    for (; e < end; e++) {
        int2 pkk = g_epack[e];
        int s = pkk.x; float a = __int_as_float(pkk.y);
        const __half* xp = xl + (size_t)s * C + lane * PC;
        float xv[PC];
        if (PC == 4) {
            uint2 u = *(const uint2*)xp;
            float2 f0 = __half22float2(*reinterpret_cast<__half2*>(&u.x));
            float2 f1 = __half22float2(*reinterpret_cast<__half2*>(&u.y));
            xv[0] = f0.x; xv[1] = f0.y; xv[2] = f1.x; xv[3] = f1.y;
        } else {
            uint32_t u = *(const uint32_t*)xp;
            float2 f0 = __half22float2(*reinterpret_cast<__half2*>(&u));
            xv[0] = f0.x; xv[1] = f0.y;
        }
        float p = 0.f;
        #pragma unroll
        for (int c = 0; c < PC; c++) {
            float v = xv[c] + xrv[c] + a * Wev[c];
            v = v > 0.f ? v : 0.2f * v;
            p += attv[c] * v;
        }
        #pragma unroll
        for (int o = 16; o; o >>= 1) p += __shfl_xor_sync(0xffffffffu, p, o);
        float wg = __expf(p);
        ssum += wg;
        #pragma unroll
        for (int c = 0; c < PC; c++) acc[c] += wg * xv[c];
    }

    float inv = 1.f / (ssum + 1e-16f);
    float ov[PC];
    #pragma unroll
    for (int c = 0; c < PC; c++) {
        float o = acc[c] * inv + bv[c];
        ov[c] = o > 0.f ? o : (__expf(o) - 1.f);          // ELU
    }
    if (PC == 4)
        *(float4*)(out + (size_t)i * C + lane * 4) = make_float4(ov[0], ov[1], ov[2], ov[3]);
    else
        *(float2*)(out + (size_t)i * C + lane * 2) = make_float2(ov[0], ov[1]);
}

// ---------------------------------------------------------------------------
extern "C" void kernel_launch(void* const* d_in, const int* in_sizes, int n_in,
                              void* d_out, int out_size) {
    const float* x    = (const float*)d_in[0];
    const int*   eidx = (const int*)  d_in[1];
    const float* ea   = (const float*)d_in[2];
    const float* Wl1  = (const float*)d_in[3];
    const float* Wr1  = (const float*)d_in[4];
    const float* We1  = (const float*)d_in[5];
    const float* att1 = (const float*)d_in[6];
    const float* b1   = (const float*)d_in[7];
    const float* Wl2  = (const float*)d_in[8];
    const float* Wr2  = (const float*)d_in[9];
    const float* We2  = (const float*)d_in[10];
    const float* att2 = (const float*)d_in[11];
    const float* b2   = (const float*)d_in[12];

    const int N = in_sizes[0] / 128;
    const int E = in_sizes[2];
    if (N > N_MAX || E > E_MAX) return;
    const int NCH = (N + 1023) / 1024;
    if (NCH > NCHUNK_MAX) return;

    const int* src = eidx;
    const int* dst = eidx + E;

    __half* p_xlh;
    float *p_xr, *p_h;
    cudaGetSymbolAddress((void**)&p_xlh, g_xlh);
    cudaGetSymbolAddress((void**)&p_xr,  g_xr);
    cudaGetSymbolAddress((void**)&p_h,   g_h);

    const size_t smA  = (size_t)128 * 132 * sizeof(float);
    const size_t sm1  = smA + (size_t)128 * 136 * sizeof(float);
    const size_t sm2d = smA + (size_t)2 * 128 * 72 * sizeof(float);
    cudaFuncSetAttribute((const void*)k_gemm_mma<128, __half>,
                         cudaFuncAttributeMaxDynamicSharedMemorySize, (int)sm1);
    cudaFuncSetAttribute((const void*)k_gemm_mma<128, float>,
                         cudaFuncAttributeMaxDynamicSharedMemorySize, (int)sm1);
    cudaFuncSetAttribute((const void*)k_gemm_mma_dual64,
                         cudaFuncAttributeMaxDynamicSharedMemorySize, (int)sm2d);

    int gemm_grid = (N + 127) / 128;
    int edge_grid = (N + 3) / 4;       // 4 warps/block, 1 warp/node

    // ---- Fork: layer-1 GEMMs (stream s1) || CSR build (default stream) ----
    cudaStream_t s1;
    cudaEvent_t evFork, evJoin;
    cudaStreamCreateWithFlags(&s1, cudaStreamNonBlocking);
    cudaEventCreateWithFlags(&evFork, cudaEventDisableTiming);
    cudaEventCreateWithFlags(&evJoin, cudaEventDisableTiming);

    cudaEventRecord(evFork, 0);
    cudaStreamWaitEvent(s1, evFork, 0);

    k_gemm_mma<128, __half><<<gemm_grid, 256, sm1, s1>>>(x, Wl1, p_xlh, N);
    k_gemm_mma<128, float ><<<gemm_grid, 256, sm1, s1>>>(x, Wr1, p_xr,  N);
    cudaEventRecord(evJoin, s1);

    k_zero   <<<(N + 255) / 256, 256>>>(N);
    k_count  <<<(E + 255) / 256, 256>>>(dst, ea, E);
    k_scan1  <<<NCH, 1024>>>(N);
    k_scan2  <<<1, 32>>>(NCH);
    k_scan3  <<<NCH, 1024>>>(N, NCH);
    k_scatter<<<(E + N + 255) / 256, 256>>>(src, dst, ea, E, N);

    cudaStreamWaitEvent(0, evJoin, 0);

    k_edge<128><<<edge_grid, 128>>>(p_xlh, p_xr, We1, att1, b1, p_h, N);
    k_gemm_mma_dual64<<<gemm_grid, 256, sm2d>>>(p_h, Wl2, Wr2, p_xlh, p_xr, N);
    k_edge<64><<<edge_grid, 128>>>(p_xlh, p_xr, We2, att2, b2, (float*)d_out, N);

    cudaEventDestroy(evFork);
    cudaEventDestroy(evJoin);
    cudaStreamDestroy(s1);
}

// round 14
// speedup vs baseline: 1.1190x; 1.0061x over previous
#include <cuda_runtime.h>
#include <cuda_fp16.h>
#include <math.h>
#include <stdint.h>

// ---------------------------------------------------------------------------
// Affinity GAT (2-layer GATv2). CSR-by-dst + fused edge kernel (direct-exp
// softmax, 1 warp/node, 4-edge unroll, fp16 xl gathers, 64-thread blocks)
// + tf32 MMA GEMMs; CSR build overlapped with layer-1 GEMMs.
// N=50000, E=800000.
// ---------------------------------------------------------------------------

#define N_MAX 51200
#define E_MAX 810000
#define EX_MAX (E_MAX + N_MAX)
#define NCHUNK_MAX 64

__device__ int   g_cnt[N_MAX];
__device__ float g_attrsum[N_MAX];
__device__ int   g_fill[N_MAX];
__device__ int   g_rowptr[N_MAX + 1];
__device__ int   g_chunksum[NCHUNK_MAX];
__device__ int   g_chunkoff[NCHUNK_MAX];
__device__ __align__(8) int2 g_epack[EX_MAX];
__device__ __align__(256) __half g_xlh[(size_t)N_MAX * 128];   // fp16 source-side features
__device__ __align__(256) float  g_xr [(size_t)N_MAX * 128];   // fp32 target-side features
__device__ __align__(256) float  g_h  [(size_t)N_MAX * 128];   // fp32 layer-1 output

// ---------------------------------------------------------------------------
__global__ void k_zero(int n) {
    int i = blockIdx.x * blockDim.x + threadIdx.x;
    if (i < n) { g_cnt[i] = 0; g_attrsum[i] = 0.f; g_fill[i] = 0; }
}

__global__ void k_count(const int* __restrict__ dst, const float* __restrict__ ea, int E) {
    int e = blockIdx.x * blockDim.x + threadIdx.x;
    if (e < E) {
        int d = dst[e];
        atomicAdd(&g_cnt[d], 1);
        atomicAdd(&g_attrsum[d], ea[e]);
    }
}

// ---- 3-phase parallel scan of (cnt[i]+1) -> rowptr ----
__global__ void k_scan1(int n) {
    __shared__ int ws[32];
    int warp = threadIdx.x >> 5, lane = threadIdx.x & 31;
    int i = blockIdx.x * 1024 + threadIdx.x;
    int v = (i < n) ? (g_cnt[i] + 1) : 0;
    #pragma unroll
    for (int o = 16; o; o >>= 1) v += __shfl_xor_sync(0xffffffffu, v, o);
    if (lane == 0) ws[warp] = v;
    __syncthreads();
    if (warp == 0) {
        int t = ws[lane];
        #pragma unroll
        for (int o = 16; o; o >>= 1) t += __shfl_xor_sync(0xffffffffu, t, o);
        if (lane == 0) g_chunksum[blockIdx.x] = t;
    }
}

__global__ void k_scan2(int nch) {
    int lane = threadIdx.x;
    int a = (lane < nch) ? g_chunksum[lane] : 0;
    int b = (lane + 32 < nch) ? g_chunksum[lane + 32] : 0;
    int ai = a, bi = b;
    #pragma unroll
    for (int o = 1; o < 32; o <<= 1) {
        int t = __shfl_up_sync(0xffffffffu, ai, o);
        if (lane >= o) ai += t;
        int u = __shfl_up_sync(0xffffffffu, bi, o);
        if (lane >= o) bi += u;
    }
    int totA = __shfl_sync(0xffffffffu, ai, 31);
    if (lane < nch)      g_chunkoff[lane]      = ai - a;
    if (lane + 32 < nch) g_chunkoff[lane + 32] = totA + bi - b;
}

__global__ void k_scan3(int n, int nch) {
    __shared__ int wsum[32];
    int warp = threadIdx.x >> 5, lane = threadIdx.x & 31;
    int i = blockIdx.x * 1024 + threadIdx.x;
    int carry = g_chunkoff[blockIdx.x];
    int v = (i < n) ? (g_cnt[i] + 1) : 0;
    int s = v;
    #pragma unroll
    for (int o = 1; o < 32; o <<= 1) {
        int t = __shfl_up_sync(0xffffffffu, s, o);
        if (lane >= o) s += t;
    }
    if (lane == 31) wsum[warp] = s;
    __syncthreads();
    if (warp == 0) {
        int ws = wsum[lane];
        #pragma unroll
        for (int o = 1; o < 32; o <<= 1) {
            int t = __shfl_up_sync(0xffffffffu, ws, o);
            if (lane >= o) ws += t;
        }
        wsum[lane] = ws;
    }
    __syncthreads();
    int warp_prefix = (warp > 0) ? wsum[warp - 1] : 0;
    if (i < n) g_rowptr[i] = carry + warp_prefix + s - v;
    if (blockIdx.x == nch - 1 && threadIdx.x == 0) g_rowptr[n] = carry + wsum[31];
}

__global__ void k_scatter(const int* __restrict__ src, const int* __restrict__ dst,
                          const float* __restrict__ ea, int E, int n) {
    int t = blockIdx.x * blockDim.x + threadIdx.x;
    if (t < E) {
        int d = dst[t];
        int pos = g_rowptr[d] + atomicAdd(&g_fill[d], 1);
        g_epack[pos] = make_int2(src[t], __float_as_int(ea[t]));
    } else if (t < E + n) {
        int i = t - E;
        int c = g_cnt[i];
        float la = g_attrsum[i] / (float)(c > 1 ? c : 1);
        int pos = g_rowptr[i] + atomicAdd(&g_fill[i], 1);
        g_epack[pos] = make_int2(i, __float_as_int(la));
    }
}

// ---------------------------------------------------------------------------
// tf32 helpers
// ---------------------------------------------------------------------------
__device__ __forceinline__ uint32_t f2tf32(float x) {
    uint32_t u;
    asm("cvt.rna.tf32.f32 %0, %1;" : "=r"(u) : "f"(x));
    return u;
}

__device__ __forceinline__ void mma_tf32(float& c0, float& c1, float& c2, float& c3,
                                         uint32_t a0, uint32_t a1, uint32_t a2, uint32_t a3,
                                         uint32_t b0, uint32_t b1) {
    asm volatile(
        "mma.sync.aligned.m16n8k8.row.col.f32.tf32.tf32.f32 "
        "{%0,%1,%2,%3}, {%4,%5,%6,%7}, {%8,%9}, {%0,%1,%2,%3};"
        : "+f"(c0), "+f"(c1), "+f"(c2), "+f"(c3)
        : "r"(a0), "r"(a1), "r"(a2), "r"(a3), "r"(b0), "r"(b1));
}

// Output store helpers (fp32 or fp16 feature matrices)
__device__ __forceinline__ void store_pair(float* out, size_t idx, float a, float b) {
    *(float2*)(out + idx) = make_float2(a, b);
}
__device__ __forceinline__ void store_pair(__half* out, size_t idx, float a, float b) {
    *(__half2*)(out + idx) = __floats2half2_rn(a, b);
}

// ---------------------------------------------------------------------------
// Single-output GEMM: out[N,NC] = A[N,128] @ W[128,NC] (tf32 mma).
// ---------------------------------------------------------------------------
template<int NC, typename OutT>
__global__ __launch_bounds__(256) void k_gemm_mma(const float* __restrict__ A,
                                                  const float* __restrict__ W,
                                                  OutT* __restrict__ out, int n) {
    constexpr int K   = 128;
    constexpr int SAS = 132;
    constexpr int SWS = (NC == 128) ? 136 : 72;
    constexpr int NT  = NC / 8;

    extern __shared__ float sh[];
    float* As = sh;
    float* Ws = sh + 128 * SAS;

    const int tid  = threadIdx.x;
    const int warp = tid >> 5;
    const int lane = tid & 31;
    const int g    = lane >> 2;
    const int t    = lane & 3;

    for (int i4 = tid; i4 < K * NC / 4; i4 += 256) {
        int idx = i4 * 4;
        int k = idx / NC, c = idx % NC;
        float4 w = *(const float4*)(W + idx);
        uint32_t* p = (uint32_t*)(Ws + k * SWS + c);
        p[0] = f2tf32(w.x); p[1] = f2tf32(w.y); p[2] = f2tf32(w.z); p[3] = f2tf32(w.w);
    }

    const int rb = blockIdx.x * 128;
    for (int i4 = tid; i4 < 128 * 32; i4 += 256) {
        int r = i4 >> 5, c = (i4 & 31) * 4;
        float4 a = make_float4(0.f, 0.f, 0.f, 0.f);
        if (rb + r < n) a = *(const float4*)(A + (size_t)(rb + r) * K + c);
        uint32_t* p = (uint32_t*)(As + r * SAS + c);
        p[0] = f2tf32(a.x); p[1] = f2tf32(a.y); p[2] = f2tf32(a.z); p[3] = f2tf32(a.w);
    }
    __syncthreads();

    float acc[NT][4];
    #pragma unroll
    for (int nt = 0; nt < NT; nt++)
        #pragma unroll
        for (int c = 0; c < 4; c++) acc[nt][c] = 0.f;

    const int r0 = warp * 16;
    const uint32_t* Au = (const uint32_t*)As;
    const uint32_t* Wu = (const uint32_t*)Ws;

    #pragma unroll 4
    for (int kk = 0; kk < K / 8; kk++) {
        int kb = kk * 8;
        uint32_t a0 = Au[(r0 + g)     * SAS + kb + t];
        uint32_t a1 = Au[(r0 + g + 8) * SAS + kb + t];
        uint32_t a2 = Au[(r0 + g)     * SAS + kb + t + 4];
        uint32_t a3 = Au[(r0 + g + 8) * SAS + kb + t + 4];
        #pragma unroll
        for (int nt = 0; nt < NT; nt++) {
            uint32_t b0 = Wu[(kb + t)     * SWS + nt * 8 + g];
            uint32_t b1 = Wu[(kb + t + 4) * SWS + nt * 8 + g];
            mma_tf32(acc[nt][0], acc[nt][1], acc[nt][2], acc[nt][3],
                     a0, a1, a2, a3, b0, b1);
        }
    }

    int row0 = rb + r0 + g;
    int row1 = row0 + 8;
    #pragma unroll
    for (int nt = 0; nt < NT; nt++) {
        int col = nt * 8 + 2 * t;
        if (row0 < n) store_pair(out, (size_t)row0 * NC + col, acc[nt][0], acc[nt][1]);
        if (row1 < n) store_pair(out, (size_t)row1 * NC + col, acc[nt][2], acc[nt][3]);
    }
}

// ---------------------------------------------------------------------------
// Dual-output GEMM (layer 2, NC=64): out1 (fp16) = A@W1, out2 (fp32) = A@W2.
// ---------------------------------------------------------------------------
__global__ __launch_bounds__(256) void k_gemm_mma_dual64(const float* __restrict__ A,
                                                         const float* __restrict__ W1,
                                                         const float* __restrict__ W2,
                                                         __half* __restrict__ out1,
                                                         float* __restrict__ out2, int n) {
    constexpr int K   = 128;
    constexpr int NC  = 64;
    constexpr int SAS = 132;
    constexpr int SWS = 72;
    constexpr int NT  = NC / 8;

    extern __shared__ float sh[];
    float* As  = sh;
    float* W1s = sh + 128 * SAS;
    float* W2s = W1s + K * SWS;

    const int tid  = threadIdx.x;
    const int warp = tid >> 5;
    const int lane = tid & 31;
    const int g    = lane >> 2;
    const int t    = lane & 3;

    for (int i4 = tid; i4 < K * NC / 4; i4 += 256) {
        int idx = i4 * 4;
        int k = idx / NC, c = idx % NC;
        float4 w1 = *(const float4*)(W1 + idx);
        float4 w2 = *(const float4*)(W2 + idx);
        uint32_t* p1 = (uint32_t*)(W1s + k * SWS + c);
        uint32_t* p2 = (uint32_t*)(W2s + k * SWS + c);
        p1[0] = f2tf32(w1.x); p1[1] = f2tf32(w1.y); p1[2] = f2tf32(w1.z); p1[3] = f2tf32(w1.w);
        p2[0] = f2tf32(w2.x); p2[1] = f2tf32(w2.y); p2[2] = f2tf32(w2.z); p2[3] = f2tf32(w2.w);
    }

    const int rb = blockIdx.x * 128;
    for (int i4 = tid; i4 < 128 * 32; i4 += 256) {
        int r = i4 >> 5, c = (i4 & 31) * 4;
        float4 a = make_float4(0.f, 0.f, 0.f, 0.f);
        if (rb + r < n) a = *(const float4*)(A + (size_t)(rb + r) * K + c);
        uint32_t* p = (uint32_t*)(As + r * SAS + c);
        p[0] = f2tf32(a.x); p[1] = f2tf32(a.y); p[2] = f2tf32(a.z); p[3] = f2tf32(a.w);
    }
    __syncthreads();

    float acc1[NT][4], acc2[NT][4];
    #pragma unroll
    for (int nt = 0; nt < NT; nt++)
        #pragma unroll
        for (int c = 0; c < 4; c++) { acc1[nt][c] = 0.f; acc2[nt][c] = 0.f; }

    const int r0 = warp * 16;
    const uint32_t* Au  = (const uint32_t*)As;
    const uint32_t* W1u = (const uint32_t*)W1s;
    const uint32_t* W2u = (const uint32_t*)W2s;

    #pragma unroll 4
    for (int kk = 0; kk < K / 8; kk++) {
        int kb = kk * 8;
        uint32_t a0 = Au[(r0 + g)     * SAS + kb + t];
        uint32_t a1 = Au[(r0 + g + 8) * SAS + kb + t];
        uint32_t a2 = Au[(r0 + g)     * SAS + kb + t + 4];
        uint32_t a3 = Au[(r0 + g + 8) * SAS + kb + t + 4];
        #pragma unroll
        for (int nt = 0; nt < NT; nt++) {
            uint32_t b0 = W1u[(kb + t)     * SWS + nt * 8 + g];
            uint32_t b1 = W1u[(kb + t + 4) * SWS + nt * 8 + g];
            mma_tf32(acc1[nt][0], acc1[nt][1], acc1[nt][2], acc1[nt][3],
                     a0, a1, a2, a3, b0, b1);
            uint32_t c0 = W2u[(kb + t)     * SWS + nt * 8 + g];
            uint32_t c1 = W2u[(kb + t + 4) * SWS + nt * 8 + g];
            mma_tf32(acc2[nt][0], acc2[nt][1], acc2[nt][2], acc2[nt][3],
                     a0, a1, a2, a3, c0, c1);
        }
    }

    int row0 = rb + r0 + g;
    int row1 = row0 + 8;
    #pragma unroll
    for (int nt = 0; nt < NT; nt++) {
        int col = nt * 8 + 2 * t;
        if (row0 < n) {
            store_pair(out1, (size_t)row0 * NC + col, acc1[nt][0], acc1[nt][1]);
            store_pair(out2, (size_t)row0 * NC + col, acc2[nt][0], acc2[nt][1]);
        }
        if (row1 < n) {
            store_pair(out1, (size_t)row1 * NC + col, acc1[nt][2], acc1[nt][3]);
            store_pair(out2, (size_t)row1 * NC + col, acc2[nt][2], acc2[nt][3]);
        }
    }
}

// ---------------------------------------------------------------------------
// Fused edge phase (R8 loop, 64-thread blocks): one warp per dst node,
// direct-exp softmax, 4-edge unroll, fp16 xl gathers.
// ---------------------------------------------------------------------------
template<int C>
__global__ __launch_bounds__(64) void k_edge(const __half* __restrict__ xl,
                                             const float* __restrict__ xr,
                                             const float* __restrict__ We,
                                             const float* __restrict__ att,
                                             const float* __restrict__ bias,
                                             float* __restrict__ out, int n) {
    constexpr int PC = C / 32;          // 4 or 2 floats per lane
    int w = (blockIdx.x * blockDim.x + threadIdx.x) >> 5;
    int lane = threadIdx.x & 31;
    if (w >= n) return;
    const int i = w;
    const int start = g_rowptr[i], end = g_rowptr[i + 1];

    float xrv[PC], Wev[PC], attv[PC], bv[PC];
    #pragma unroll
    for (int c = 0; c < PC; c++) {
        int col = lane * PC + c;
        xrv[c]  = xr[(size_t)i * C + col];
        Wev[c]  = We[col];
        attv[c] = att[col];
        bv[c]   = bias[col];
    }

    float ssum = 0.f;
    float acc[PC];
    #pragma unroll
    for (int c = 0; c < PC; c++) acc[c] = 0.f;

    int e = start;
    for (; e + 4 <= end; e += 4) {
        int2 pk[4];
        #pragma unroll
        for (int j = 0; j < 4; j++) pk[j] = g_epack[e + j];

        float xv[4][PC];
        #pragma unroll
        for (int j = 0; j < 4; j++) {
            const __half* xp = xl + (size_t)pk[j].x * C + lane * PC;
            if (PC == 4) {
                uint2 u = *(const uint2*)xp;
                float2 f0 = __half22float2(*reinterpret_cast<__half2*>(&u.x));
                float2 f1 = __half22float2(*reinterpret_cast<__half2*>(&u.y));
                xv[j][0] = f0.x; xv[j][1] = f0.y; xv[j][2] = f1.x; xv[j][3] = f1.y;
            } else {
                uint32_t u = *(const uint32_t*)xp;
                float2 f0 = __half22float2(*reinterpret_cast<__half2*>(&u));
                xv[j][0] = f0.x; xv[j][1] = f0.y;
            }
        }

        float p[4];
        #pragma unroll
        for (int j = 0; j < 4; j++) {
            float a = __int_as_float(pk[j].y);
            float s = 0.f;
            #pragma unroll
            for (int c = 0; c < PC; c++) {
                float u = xv[j][c] + xrv[c] + a * Wev[c];
                u = u > 0.f ? u : 0.2f * u;               // leaky_relu(0.2)
                s += attv[c] * u;
            }
            p[j] = s;
        }
        #pragma unroll
        for (int o = 16; o; o >>= 1) {
            #pragma unroll
            for (int j = 0; j < 4; j++)
                p[j] += __shfl_xor_sync(0xffffffffu, p[j], o);
        }

        float wg[4];
        #pragma unroll
        for (int j = 0; j < 4; j++) wg[j] = __expf(p[j]);
        ssum += (wg[0] + wg[1]) + (wg[2] + wg[3]);
        #pragma unroll
        for (int c = 0; c < PC; c++) {
            float t0 = wg[0] * xv[0][c] + wg[1] * xv[1][c];
            float t1 = wg[2] * xv[2][c] + wg[3] * xv[3][c];
            acc[c] += t0 + t1;
        }
    }
    for (; e < end; e++) {
        int2 pkk = g_epack[e];
        int s = pkk.x; float a = __int_as_float(pkk.y);
        const __half* xp = xl + (size_t)s * C + lane * PC;
        float xv[PC];
        if (PC == 4) {
            uint2 u = *(const uint2*)xp;
            float2 f0 = __half22float2(*reinterpret_cast<__half2*>(&u.x));
            float2 f1 = __half22float2(*reinterpret_cast<__half2*>(&u.y));
            xv[0] = f0.x; xv[1] = f0.y; xv[2] = f1.x; xv[3] = f1.y;
        } else {
            uint32_t u = *(const uint32_t*)xp;
            float2 f0 = __half22float2(*reinterpret_cast<__half2*>(&u));
            xv[0] = f0.x; xv[1] = f0.y;
        }
        float p = 0.f;
        #pragma unroll
        for (int c = 0; c < PC; c++) {
            float v = xv[c] + xrv[c] + a * Wev[c];
            v = v > 0.f ? v : 0.2f * v;
            p += attv[c] * v;
        }
        #pragma unroll
        for (int o = 16; o; o >>= 1) p += __shfl_xor_sync(0xffffffffu, p, o);
        float wg = __expf(p);
        ssum += wg;
        #pragma unroll
        for (int c = 0; c < PC; c++) acc[c] += wg * xv[c];
    }

    float inv = 1.f / (ssum + 1e-16f);
    float ov[PC];
    #pragma unroll
    for (int c = 0; c < PC; c++) {
        float o = acc[c] * inv + bv[c];
        ov[c] = o > 0.f ? o : (__expf(o) - 1.f);          // ELU
    }
    if (PC == 4)
        *(float4*)(out + (size_t)i * C + lane * 4) = make_float4(ov[0], ov[1], ov[2], ov[3]);
    else
        *(float2*)(out + (size_t)i * C + lane * 2) = make_float2(ov[0], ov[1]);
}

// ---------------------------------------------------------------------------
extern "C" void kernel_launch(void* const* d_in, const int* in_sizes, int n_in,
                              void* d_out, int out_size) {
    const float* x    = (const float*)d_in[0];
    const int*   eidx = (const int*)  d_in[1];
    const float* ea   = (const float*)d_in[2];
    const float* Wl1  = (const float*)d_in[3];
    const float* Wr1  = (const float*)d_in[4];
    const float* We1  = (const float*)d_in[5];
    const float* att1 = (const float*)d_in[6];
    const float* b1   = (const float*)d_in[7];
    const float* Wl2  = (const float*)d_in[8];
    const float* Wr2  = (const float*)d_in[9];
    const float* We2  = (const float*)d_in[10];
    const float* att2 = (const float*)d_in[11];
    const float* b2   = (const float*)d_in[12];

    const int N = in_sizes[0] / 128;
    const int E = in_sizes[2];
    if (N > N_MAX || E > E_MAX) return;
    const int NCH = (N + 1023) / 1024;
    if (NCH > NCHUNK_MAX) return;

    const int* src = eidx;
    const int* dst = eidx + E;

    __half* p_xlh;
    float *p_xr, *p_h;
    cudaGetSymbolAddress((void**)&p_xlh, g_xlh);
    cudaGetSymbolAddress((void**)&p_xr,  g_xr);
    cudaGetSymbolAddress((void**)&p_h,   g_h);

    const size_t smA  = (size_t)128 * 132 * sizeof(float);
    const size_t sm1  = smA + (size_t)128 * 136 * sizeof(float);
    const size_t sm2d = smA + (size_t)2 * 128 * 72 * sizeof(float);
    cudaFuncSetAttribute((const void*)k_gemm_mma<128, __half>,
                         cudaFuncAttributeMaxDynamicSharedMemorySize, (int)sm1);
    cudaFuncSetAttribute((const void*)k_gemm_mma<128, float>,
                         cudaFuncAttributeMaxDynamicSharedMemorySize, (int)sm1);
    cudaFuncSetAttribute((const void*)k_gemm_mma_dual64,
                         cudaFuncAttributeMaxDynamicSharedMemorySize, (int)sm2d);

    int gemm_grid = (N + 127) / 128;
    int edge_grid = (N + 1) / 2;       // 2 warps/block, 1 warp/node

    // ---- Fork: layer-1 GEMMs (stream s1) || CSR build (default stream) ----
    cudaStream_t s1;
    cudaEvent_t evFork, evJoin;
    cudaStreamCreateWithFlags(&s1, cudaStreamNonBlocking);
    cudaEventCreateWithFlags(&evFork, cudaEventDisableTiming);
    cudaEventCreateWithFlags(&evJoin, cudaEventDisableTiming);

    cudaEventRecord(evFork, 0);
    cudaStreamWaitEvent(s1, evFork, 0);

    k_gemm_mma<128, __half><<<gemm_grid, 256, sm1, s1>>>(x, Wl1, p_xlh, N);
    k_gemm_mma<128, float ><<<gemm_grid, 256, sm1, s1>>>(x, Wr1, p_xr,  N);
    cudaEventRecord(evJoin, s1);

    k_zero   <<<(N + 255) / 256, 256>>>(N);
    k_count  <<<(E + 255) / 256, 256>>>(dst, ea, E);
    k_scan1  <<<NCH, 1024>>>(N);
    k_scan2  <<<1, 32>>>(NCH);
    k_scan3  <<<NCH, 1024>>>(N, NCH);
    k_scatter<<<(E + N + 255) / 256, 256>>>(src, dst, ea, E, N);

    cudaStreamWaitEvent(0, evJoin, 0);

    k_edge<128><<<edge_grid, 64>>>(p_xlh, p_xr, We1, att1, b1, p_h, N);
    k_gemm_mma_dual64<<<gemm_grid, 256, sm2d>>>(p_h, Wl2, Wr2, p_xlh, p_xr, N);
    k_edge<64><<<edge_grid, 64>>>(p_xlh, p_xr, We2, att2, b2, (float*)d_out, N);

    cudaEventDestroy(evFork);
    cudaEventDestroy(evJoin);
    cudaStreamDestroy(s1);
}